// round 10
// baseline (speedup 1.0000x reference)
#include <cuda_runtime.h>
#include <cuda_bf16.h>
#include <cstdint>

// out[n,R,C,co] = active[n,R/14,C/14] * (bias[co] + sum_{dy,dx,ci} x[n,R+dy,C+dx,ci]*k[dy,dx,ci,co])
// valid 3x3 conv 506x506 -> 504x504, gated per 14x14 tile by mask-block max > 0.5
//
// mma.sync bf16 (fp32 = hi+lo bf16, 3 products), persistent warp-specialized CTAs:
//   448 thr: warps 0-11 consumers (tile 16x24, warp = 4 cols x 16 rows x 16 co,
//   co-split -> exactly 3 consumers/SMSP), warps 12-13 producers (double-buffered X).
//   XOR-swizzled smem (128B pitch, no pads): chunk t ^= (rowkey & 7).
//   A-fragments loaded once per (dy,h), reused across the 3 dx taps.

#define N_IMG 8
#define H_IN  506
#define W_IN  506
#define H_OUT 504
#define W_OUT 504
#define NBH   36
#define NBW   36

#define RT_CNT 32                     // 16-row tiles (rows 496.. guarded)
#define CT_CNT 21                     // 24-col tiles: 21*24 = 504 exact
#define TPI    (RT_CNT * CT_CNT)      // 672
#define N_TILES (N_IMG * TPI)         // 5376
#define GRID_CONV 148

#define THREADS 448
#define NCONS   384                   // 12 consumer warps

#define XROWP 26                      // pixel columns per row (24 + 2 halo)
#define PIXB  128                     // 64B hi(ci0-31) | 64B lo, swizzled
#define XS_BYTES (18 * XROWP * PIXB)  // 59904 per buffer
#define WS_BYTES (9 * 32 * 128)       // 36864
#define SMEM_BYTES (2 * XS_BYTES + WS_BYTES)   // 156672

__device__ float g_active[N_IMG * NBH * NBW];

// ------------------------- helpers ------------------------------------------
__device__ __forceinline__ uint32_t smem_u32(const void* p) {
    uint32_t a;
    asm("{ .reg .u64 t; cvta.to.shared.u64 t, %1; cvt.u32.u64 %0, t; }"
        : "=r"(a) : "l"(p));
    return a;
}
__device__ __forceinline__ void sts64(uint32_t a, uint64_t v) {
    asm volatile("st.shared.b64 [%0], %1;" :: "r"(a), "l"(v) : "memory");
}
__device__ __forceinline__ void sts128(uint32_t a, uint32_t r0, uint32_t r1,
                                       uint32_t r2, uint32_t r3) {
    asm volatile("st.shared.v4.b32 [%0], {%1,%2,%3,%4};"
                 :: "r"(a), "r"(r0), "r"(r1), "r"(r2), "r"(r3) : "memory");
}
__device__ __forceinline__ void ldsm4(uint32_t* r, uint32_t addr) {
    asm volatile("ldmatrix.sync.aligned.m8n8.x4.shared.b16 {%0,%1,%2,%3}, [%4];"
                 : "=r"(r[0]), "=r"(r[1]), "=r"(r[2]), "=r"(r[3]) : "r"(addr));
}
__device__ __forceinline__ void mma4(float* d, const uint32_t* a, const uint32_t* b) {
    asm volatile(
        "mma.sync.aligned.m16n8k16.row.col.f32.bf16.bf16.f32 "
        "{%0,%1,%2,%3},{%4,%5,%6,%7},{%8,%9},{%0,%1,%2,%3};"
        : "+f"(d[0]), "+f"(d[1]), "+f"(d[2]), "+f"(d[3])
        : "r"(a[0]), "r"(a[1]), "r"(a[2]), "r"(a[3]), "r"(b[0]), "r"(b[1]));
}
__device__ __forceinline__ unsigned short bf_hi(float f) {
    return __bfloat16_as_ushort(__float2bfloat16_rn(f));
}

// ---------------- kernel 1: mask block max -> active flag -------------------
__global__ void __launch_bounds__(256) mask_kernel(const float* __restrict__ mask) {
    __shared__ float red[256];
    int b = blockIdx.x;
    int n   = b / (NBH * NBW);
    int rem = b % (NBH * NBW);
    int bi = rem / NBW, bj = rem % NBW;
    int tid = threadIdx.x;
    int rr = tid >> 4, cc = tid & 15;
    red[tid] = mask[(n * H_IN + bi * 14 + rr) * W_IN + bj * 14 + cc];
    __syncthreads();
    #pragma unroll
    for (int s = 128; s > 0; s >>= 1) {
        if (tid < s) red[tid] = fmaxf(red[tid], red[tid + s]);
        __syncthreads();
    }
    if (tid == 0) g_active[b] = (red[0] > 0.5f) ? 1.0f : 0.0f;
}

// ---------------- producer: stage one tile's x into buffer ------------------
__device__ __forceinline__ void produce_tile(
    const float* __restrict__ x, uint32_t xb, int n, int R0, int C0, int ptid)
{
    // 18 rows x 26 cols pixels, 32 ci each, hi/lo bf16, swizzled chunks
    for (int p = ptid; p < 18 * 26; p += 64) {
        int ir = p / 26, ic = p - ir * 26;
        int gr = R0 + ir; if (gr > H_IN - 1) gr = H_IN - 1;
        int gc = C0 + ic;                 // C0<=480, ic<=25 -> <=505 in range
        const float4* gp = (const float4*)
            (x + (((size_t)n * H_IN + gr) * W_IN + gc) * 32);
        float4 v[8];
        #pragma unroll
        for (int q = 0; q < 8; q++) v[q] = gp[q];
        uint32_t a = xb + (uint32_t)((ir * XROWP + ic) * PIXB);
        uint32_t s = (uint32_t)(ir & 7);
        #pragma unroll
        for (int o = 0; o < 4; o++) {
            float fv[8] = {v[2*o].x, v[2*o].y, v[2*o].z, v[2*o].w,
                           v[2*o+1].x, v[2*o+1].y, v[2*o+1].z, v[2*o+1].w};
            uint32_t hi[4], lo[4];
            #pragma unroll
            for (int q = 0; q < 4; q++) {
                float f0 = fv[2*q], f1 = fv[2*q+1];
                __nv_bfloat162 h = __floats2bfloat162_rn(f0, f1);
                float r0 = f0 - __bfloat162float(h.x);
                float r1 = f1 - __bfloat162float(h.y);
                __nv_bfloat162 lw = __floats2bfloat162_rn(r0, r1);
                hi[q] = *reinterpret_cast<uint32_t*>(&h);
                lo[q] = *reinterpret_cast<uint32_t*>(&lw);
            }
            uint32_t hiA = a + ((((uint32_t)o) ^ s) << 4);          // chunk o
            sts128(hiA,      hi[0], hi[1], hi[2], hi[3]);
            sts128(hiA ^ 64, lo[0], lo[1], lo[2], lo[3]);           // chunk o+4
        }
    }
}

// ---------------- kernel 2: persistent warp-specialized conv ----------------
__global__ void __launch_bounds__(THREADS, 1) conv_mma_kernel(
    const float* __restrict__ x,
    const float* __restrict__ kern,
    const float* __restrict__ bias,
    float* __restrict__ out)
{
    extern __shared__ char smem[];
    const uint32_t xs0 = smem_u32(smem);
    const uint32_t ws  = xs0 + 2 * XS_BYTES;
    const int tid = threadIdx.x;
    const int wid = tid >> 5;
    const int lid = tid & 31;
    const int bid = blockIdx.x;

    // ---- stage weights once: ws[tap][co][hi ci | lo ci], swizzled by co&7 ----
    for (int j = tid; j < 2304; j += THREADS) {
        int ciq = j & 7;
        int co  = (j >> 3) & 31;
        int tap = j >> 8;
        int ci  = ciq * 4;
        const float* kp = kern + (tap * 32 + ci) * 32 + co;
        float f0 = kp[0], f1 = kp[32], f2 = kp[64], f3 = kp[96];
        unsigned short h0 = bf_hi(f0), h1 = bf_hi(f1), h2 = bf_hi(f2), h3 = bf_hi(f3);
        unsigned short l0 = bf_hi(f0 - __bfloat162float(__ushort_as_bfloat16(h0)));
        unsigned short l1 = bf_hi(f1 - __bfloat162float(__ushort_as_bfloat16(h1)));
        unsigned short l2 = bf_hi(f2 - __bfloat162float(__ushort_as_bfloat16(h2)));
        unsigned short l3 = bf_hi(f3 - __bfloat162float(__ushort_as_bfloat16(h3)));
        uint64_t hi64 = (uint64_t)h0 | ((uint64_t)h1 << 16)
                      | ((uint64_t)h2 << 32) | ((uint64_t)h3 << 48);
        uint64_t lo64 = (uint64_t)l0 | ((uint64_t)l1 << 16)
                      | ((uint64_t)l2 << 32) | ((uint64_t)l3 << 48);
        // byte off b = ciq*8 within the 64B hi half; chunk = ciq>>1, swizzle ^ (co&7)
        uint32_t a = ws + (uint32_t)((tap * 32 + co) * 128)
                   + (uint32_t)(((ciq >> 1) ^ (co & 7)) << 4) + (uint32_t)((ciq & 1) * 8);
        sts64(a, hi64);
        sts64(a ^ 64, lo64);            // lo chunk = (ciq>>1)+4
    }

    const int nT = (N_TILES - bid + GRID_CONV - 1) / GRID_CONV;

    if (wid >= 12) {
        // ================= PRODUCER warps (12,13) =================
        const int ptid = tid - NCONS;
        {
            int t = bid;
            int n = t / TPI, rem = t % TPI;
            produce_tile(x, xs0, n, (rem / CT_CNT) * 16, (rem % CT_CNT) * 24, ptid);
        }
        for (int k = 0; k < nT; k++) {
            __syncthreads();            // buf[k&1] full, handed to consumers
            int k1 = k + 1;
            if (k1 < nT) {
                int t = bid + k1 * GRID_CONV;
                int n = t / TPI, rem = t % TPI;
                produce_tile(x, xs0 + (k1 & 1) * XS_BYTES, n,
                             (rem / CT_CNT) * 16, (rem % CT_CNT) * 24, ptid);
            }
        }
        return;
    }

    // ================= CONSUMER warps (0-11) =================
    const int cg  = wid % 6;            // column group: cols cg*4 .. cg*4+3
    const int coH = wid / 6;            // cout half: 0 -> co 0-15, 1 -> co 16-31
    const int cw  = cg * 4;

    const int irl = (lid & 7) + 8 * ((lid >> 3) & 1);   // lane's M-row 0..15
    const uint32_t baseArow = (uint32_t)((irl * XROWP + cw) * PIXB);
    const uint32_t cA = (uint32_t)((lid >> 4) & 1);     // A chunk bit0

    const uint32_t sB = (uint32_t)(lid & 7);            // B swizzle key (co&7)
    const uint32_t bB0 = (uint32_t)((lid >> 3) & 1);    // B chunk bit0
    const uint32_t baseBrow = ws + (uint32_t)
        ((((lid & 7) + ((lid >> 4) << 3) + coH * 16)) * 128);
    const uint32_t offB0 = ((bB0 ^ sB) << 4);           // h -> ^32, lo -> ^64

    const int n2 = (lid & 3) * 2;
    float2 bv[2];
    #pragma unroll
    for (int nb = 0; nb < 2; nb++)
        bv[nb] = *(const float2*)(bias + coH * 16 + nb * 8 + n2);

    for (int k = 0; k < nT; k++) {
        __syncthreads();                // buf[k&1] ready
        const int t   = bid + k * GRID_CONV;
        const int n   = t / TPI;
        const int rem = t % TPI;
        const int R0 = (rem / CT_CNT) * 16;
        const int C0 = (rem % CT_CNT) * 24;
        const uint32_t xb = xs0 + (k & 1) * XS_BYTES;

        float d[4][2][4];
        #pragma unroll
        for (int f = 0; f < 4; f++)
            #pragma unroll
            for (int nb = 0; nb < 2; nb++)
                #pragma unroll
                for (int e = 0; e < 4; e++) d[f][nb][e] = 0.0f;

        #pragma unroll 1
        for (int dy = 0; dy < 3; dy++) {
            const uint32_t arow = xb + baseArow + (uint32_t)(dy * XROWP * PIXB);
            const uint32_t offA0 = ((cA ^ (uint32_t)((irl + dy) & 7)) << 4);
            #pragma unroll 1
            for (int h = 0; h < 2; h++) {
                const uint32_t offA = offA0 ^ ((uint32_t)h << 5);
                uint32_t Ah[24], Al[24], Bh[4], Bl[4];
                #pragma unroll
                for (int j = 0; j < 6; j++) {
                    ldsm4(Ah + 4 * j, arow + j * PIXB + offA);
                    ldsm4(Al + 4 * j, (arow + j * PIXB + offA) ^ 64);
                }
                const uint32_t offB = offB0 ^ ((uint32_t)h << 5);
                #pragma unroll
                for (int dx = 0; dx < 3; dx++) {
                    const uint32_t bo = baseBrow
                        + (uint32_t)((dy * 3 + dx) * (32 * 128)) + offB;
                    ldsm4(Bh, bo);
                    ldsm4(Bl, bo ^ 64);
                    #pragma unroll
                    for (int f = 0; f < 4; f++)
                        #pragma unroll
                        for (int nb = 0; nb < 2; nb++)
                            mma4(d[f][nb], Ah + 4 * (f + dx), Bh + 2 * nb);
                    #pragma unroll
                    for (int f = 0; f < 4; f++)
                        #pragma unroll
                        for (int nb = 0; nb < 2; nb++)
                            mma4(d[f][nb], Ah + 4 * (f + dx), Bl + 2 * nb);
                    #pragma unroll
                    for (int f = 0; f < 4; f++)
                        #pragma unroll
                        for (int nb = 0; nb < 2; nb++)
                            mma4(d[f][nb], Al + 4 * (f + dx), Bh + 2 * nb);
                }
            }
        }

        // ---- epilogue (cols exact: 21*24 = 504; rows guarded) ----
        const int r0 = lid >> 2;
        const int R1 = R0 + r0;
        const int R2 = R1 + 8;
        const bool r2ok = (R2 < H_OUT);
        const int R2c = r2ok ? R2 : H_OUT - 1;
        const float* act1 = g_active + (n * NBH + R1 / 14) * NBW;
        const float* act2 = g_active + (n * NBH + R2c / 14) * NBW;

        #pragma unroll
        for (int f = 0; f < 4; f++) {
            const int C = C0 + cw + f;
            const int cb = C / 14;
            float fg1 = act1[cb];
            float* o1 = out + (((size_t)n * H_OUT + R1) * W_OUT + C) * 32
                      + coH * 16 + n2;
            #pragma unroll
            for (int nb = 0; nb < 2; nb++) {
                float2 v;
                v.x = (d[f][nb][0] + bv[nb].x) * fg1;
                v.y = (d[f][nb][1] + bv[nb].y) * fg1;
                *(float2*)(o1 + nb * 8) = v;
            }
            if (r2ok) {
                float fg2 = act2[cb];
                float* o2 = out + (((size_t)n * H_OUT + R2) * W_OUT + C) * 32
                          + coH * 16 + n2;
                #pragma unroll
                for (int nb = 0; nb < 2; nb++) {
                    float2 v;
                    v.x = (d[f][nb][2] + bv[nb].x) * fg2;
                    v.y = (d[f][nb][3] + bv[nb].y) * fg2;
                    *(float2*)(o2 + nb * 8) = v;
                }
            }
        }
    }
}

// ---------------------------------------------------------------------------
extern "C" void kernel_launch(void* const* d_in, const int* in_sizes, int n_in,
                              void* d_out, int out_size)
{
    const float* x    = (const float*)d_in[0];
    const float* mask = (const float*)d_in[1];
    const float* kern = (const float*)d_in[2];
    const float* bias = (const float*)d_in[3];
    float* out = (float*)d_out;
    (void)in_sizes; (void)n_in; (void)out_size;

    cudaFuncSetAttribute(conv_mma_kernel,
                         cudaFuncAttributeMaxDynamicSharedMemorySize, SMEM_BYTES);

    mask_kernel<<<N_IMG * NBH * NBW, 256>>>(mask);
    conv_mma_kernel<<<GRID_CONV, THREADS, SMEM_BYTES>>>(x, kern, bias, out);
}

// round 11
// speedup vs baseline: 1.7813x; 1.7813x over previous
#include <cuda_runtime.h>
#include <cuda_fp16.h>
#include <cstdint>

// out[n,R,C,co] = active[n,R/14,C/14] * (bias[co] + sum_{dy,dx,ci} x[n,R+dy,C+dx,ci]*k[dy,dx,ci,co])
// valid 3x3 conv 506x506 -> 504x504, gated per 14x14 tile by mask-block max > 0.5
//
// mma.sync fp16 single-product (A,B quantized to fp16; norm rel err ~4e-4 < 1e-3).
// Persistent CTAs, 2 CTAs/SM, 256 thr, tile 16x32, warp = 4 cols x 16 rows x 32 co.
// A-fragments loaded once per (dy,h), reused across the 3 dx taps.

#define N_IMG 8
#define H_IN  506
#define W_IN  506
#define H_OUT 504
#define W_OUT 504
#define NBH   36
#define NBW   36

#define RT_CNT 32                     // 16-row tiles (rows 496.. guarded)
#define CT_CNT 16                     // 32-col tiles (cols 480.. guarded)
#define TPI    (RT_CNT * CT_CNT)      // 512
#define N_TILES (N_IMG * TPI)         // 4096
#define GRID_CONV 296

#define THREADS 256

#define XROWP 35                      // pixel-column pitch (odd -> conflict-free)
#define PIXB  80                      // 64B fp16 ci0-31 + 16 pad (odd 16B pitch)
#define XS_BYTES (18 * XROWP * PIXB)  // 50400
#define WROWB 80                      // 64B fp16 ci + 16 pad
#define WS_BYTES (9 * 32 * WROWB)     // 23040
#define SMEM_BYTES (XS_BYTES + WS_BYTES)   // 73440 -> 2 CTAs/SM

__device__ float g_active[N_IMG * NBH * NBW];

// ------------------------- helpers ------------------------------------------
__device__ __forceinline__ uint32_t smem_u32(const void* p) {
    uint32_t a;
    asm("{ .reg .u64 t; cvta.to.shared.u64 t, %1; cvt.u32.u64 %0, t; }"
        : "=r"(a) : "l"(p));
    return a;
}
__device__ __forceinline__ void sts64(uint32_t a, uint64_t v) {
    asm volatile("st.shared.b64 [%0], %1;" :: "r"(a), "l"(v) : "memory");
}
__device__ __forceinline__ void sts128(uint32_t a, uint32_t r0, uint32_t r1,
                                       uint32_t r2, uint32_t r3) {
    asm volatile("st.shared.v4.b32 [%0], {%1,%2,%3,%4};"
                 :: "r"(a), "r"(r0), "r"(r1), "r"(r2), "r"(r3) : "memory");
}
__device__ __forceinline__ void ldsm4(uint32_t* r, uint32_t addr) {
    asm volatile("ldmatrix.sync.aligned.m8n8.x4.shared.b16 {%0,%1,%2,%3}, [%4];"
                 : "=r"(r[0]), "=r"(r[1]), "=r"(r[2]), "=r"(r[3]) : "r"(addr));
}
__device__ __forceinline__ void mma4(float* d, const uint32_t* a, const uint32_t* b) {
    asm volatile(
        "mma.sync.aligned.m16n8k16.row.col.f32.f16.f16.f32 "
        "{%0,%1,%2,%3},{%4,%5,%6,%7},{%8,%9},{%0,%1,%2,%3};"
        : "+f"(d[0]), "+f"(d[1]), "+f"(d[2]), "+f"(d[3])
        : "r"(a[0]), "r"(a[1]), "r"(a[2]), "r"(a[3]), "r"(b[0]), "r"(b[1]));
}

// ---------------- kernel 1: mask block max -> active flag -------------------
__global__ void __launch_bounds__(256) mask_kernel(const float* __restrict__ mask) {
    __shared__ float red[256];
    int b = blockIdx.x;
    int n   = b / (NBH * NBW);
    int rem = b % (NBH * NBW);
    int bi = rem / NBW, bj = rem % NBW;
    int tid = threadIdx.x;
    int rr = tid >> 4, cc = tid & 15;
    red[tid] = mask[(n * H_IN + bi * 14 + rr) * W_IN + bj * 14 + cc];
    __syncthreads();
    #pragma unroll
    for (int s = 128; s > 0; s >>= 1) {
        if (tid < s) red[tid] = fmaxf(red[tid], red[tid + s]);
        __syncthreads();
    }
    if (tid == 0) g_active[b] = (red[0] > 0.5f) ? 1.0f : 0.0f;
}

// ---------------- kernel 2: persistent conv via mma.sync fp16 ---------------
__global__ void __launch_bounds__(THREADS, 2) conv_mma_kernel(
    const float* __restrict__ x,
    const float* __restrict__ kern,
    const float* __restrict__ bias,
    float* __restrict__ out)
{
    extern __shared__ char smem[];
    const uint32_t xs = smem_u32(smem);
    const uint32_t ws = xs + XS_BYTES;
    const int tid = threadIdx.x;
    const int wid = tid >> 5;
    const int lid = tid & 31;

    // ---- stage weights once: kern[tap][ci][co] -> ws[tap][co][ci fp16] ----
    for (int j = tid; j < 2304; j += THREADS) {
        int ciq = j & 7;
        int co  = (j >> 3) & 31;
        int tap = j >> 8;
        int ci  = ciq * 4;
        const float* kp = kern + (tap * 32 + ci) * 32 + co;
        __half2 p0 = __floats2half2_rn(kp[0],  kp[32]);
        __half2 p1 = __floats2half2_rn(kp[64], kp[96]);
        uint64_t v = (uint64_t)(*reinterpret_cast<uint32_t*>(&p0))
                   | ((uint64_t)(*reinterpret_cast<uint32_t*>(&p1)) << 32);
        sts64(ws + (uint32_t)((tap * 32 + co) * WROWB + ciq * 8), v);
    }

    // per-lane ldmatrix base addresses
    const int cw = wid * 4;
    const int irl = (lid & 7) + 8 * ((lid >> 3) & 1);
    const uint32_t baseA = xs + (uint32_t)
        ((irl * XROWP + cw) * PIXB + ((lid >> 4) & 1) * 16);
    const uint32_t baseB = ws + (uint32_t)
        ((((lid & 7) + ((lid >> 4) << 3)) * WROWB) + ((lid >> 3) & 1) * 16);

    // bias fragment (invariant)
    const int n2 = (lid & 3) * 2;
    float2 bv[4];
    #pragma unroll
    for (int nb = 0; nb < 4; nb++)
        bv[nb] = *(const float2*)(bias + nb * 8 + n2);

    for (int t = blockIdx.x; t < N_TILES; t += GRID_CONV) {
        const int n   = t / TPI;
        const int rem = t % TPI;
        const int R0 = (rem >> 4) * 16;
        const int C0 = (rem & 15) * 32;

        __syncthreads();   // previous iteration's readers done before overwrite

        // ---- stage x: 18 rows x 34 cols x 32 ci fp16 (oct-outer) ----
        for (int j = tid; j < 2448; j += THREADS) {
            int oct = j / 612;                 // 8-ci group
            int p   = j - oct * 612;
            int ir = p / 34, ic = p - ir * 34;
            int gr = R0 + ir; if (gr > H_IN - 1) gr = H_IN - 1;
            int gc = C0 + ic; if (gc > W_IN - 1) gc = W_IN - 1;
            const float4* gp = (const float4*)
                (x + (((size_t)n * H_IN + gr) * W_IN + gc) * 32 + oct * 8);
            float4 va = gp[0], vb = gp[1];
            __half2 h0 = __floats2half2_rn(va.x, va.y);
            __half2 h1 = __floats2half2_rn(va.z, va.w);
            __half2 h2 = __floats2half2_rn(vb.x, vb.y);
            __half2 h3 = __floats2half2_rn(vb.z, vb.w);
            sts128(xs + (uint32_t)((ir * XROWP + ic) * PIXB + oct * 16),
                   *reinterpret_cast<uint32_t*>(&h0),
                   *reinterpret_cast<uint32_t*>(&h1),
                   *reinterpret_cast<uint32_t*>(&h2),
                   *reinterpret_cast<uint32_t*>(&h3));
        }
        __syncthreads();

        // ---- main loop: dy x h, A-frags shared across dx, single product ----
        float d[4][4][4];
        #pragma unroll
        for (int f = 0; f < 4; f++)
            #pragma unroll
            for (int nb = 0; nb < 4; nb++)
                #pragma unroll
                for (int e = 0; e < 4; e++) d[f][nb][e] = 0.0f;

        #pragma unroll 1
        for (int dy = 0; dy < 3; dy++) {
            #pragma unroll
            for (int h = 0; h < 2; h++) {
                uint32_t A[24], B[8];
                const uint32_t ao = baseA + (uint32_t)(dy * XROWP * PIXB + h * 32);
                #pragma unroll
                for (int j = 0; j < 6; j++)
                    ldsm4(A + 4 * j, ao + j * PIXB);
                #pragma unroll
                for (int dx = 0; dx < 3; dx++) {
                    const uint32_t bo = baseB
                        + (uint32_t)((dy * 3 + dx) * (32 * WROWB) + h * 32);
                    ldsm4(B,     bo);
                    ldsm4(B + 4, bo + 16 * WROWB);
                    #pragma unroll
                    for (int f = 0; f < 4; f++)
                        #pragma unroll
                        for (int nb = 0; nb < 4; nb++)
                            mma4(d[f][nb], A + 4 * (f + dx), B + 2 * nb);
                }
            }
        }

        // ---- epilogue ----
        const int r0 = lid >> 2;
        const int R1 = R0 + r0;
        const int R2 = R1 + 8;
        const bool r2ok = (R2 < H_OUT);
        const int R2c = r2ok ? R2 : H_OUT - 1;
        const float* act1 = g_active + (n * NBH + R1 / 14) * NBW;
        const float* act2 = g_active + (n * NBH + R2c / 14) * NBW;

        #pragma unroll
        for (int f = 0; f < 4; f++) {
            const int C = C0 + cw + f;
            if (C < W_OUT) {
                const int cb = C / 14;
                float fg1 = act1[cb];
                float* o1 = out + (((size_t)n * H_OUT + R1) * W_OUT + C) * 32 + n2;
                #pragma unroll
                for (int nb = 0; nb < 4; nb++) {
                    float2 v;
                    v.x = (d[f][nb][0] + bv[nb].x) * fg1;
                    v.y = (d[f][nb][1] + bv[nb].y) * fg1;
                    *(float2*)(o1 + nb * 8) = v;
                }
                if (r2ok) {
                    float fg2 = act2[cb];
                    float* o2 = out + (((size_t)n * H_OUT + R2) * W_OUT + C) * 32 + n2;
                    #pragma unroll
                    for (int nb = 0; nb < 4; nb++) {
                        float2 v;
                        v.x = (d[f][nb][2] + bv[nb].x) * fg2;
                        v.y = (d[f][nb][3] + bv[nb].y) * fg2;
                        *(float2*)(o2 + nb * 8) = v;
                    }
                }
            }
        }
    }
}

// ---------------------------------------------------------------------------
extern "C" void kernel_launch(void* const* d_in, const int* in_sizes, int n_in,
                              void* d_out, int out_size)
{
    const float* x    = (const float*)d_in[0];
    const float* mask = (const float*)d_in[1];
    const float* kern = (const float*)d_in[2];
    const float* bias = (const float*)d_in[3];
    float* out = (float*)d_out;
    (void)in_sizes; (void)n_in; (void)out_size;

    cudaFuncSetAttribute(conv_mma_kernel,
                         cudaFuncAttributeMaxDynamicSharedMemorySize, SMEM_BYTES);

    mask_kernel<<<N_IMG * NBH * NBW, 256>>>(mask);
    conv_mma_kernel<<<GRID_CONV, THREADS, SMEM_BYTES>>>(x, kern, bias, out);
}